// round 7
// baseline (speedup 1.0000x reference)
#include <cuda_runtime.h>
#include <cuda_bf16.h>
#include <stdint.h>

#define BB 2
#define SS 2048
#define DM 1024
#define NH 16
#define DH 64
#define WSZ (NH * DM * DH)
#define LOG2E 1.4426950408889634f

// Pre-split inputs (hi/lo bf16)
__device__ __nv_bfloat16 g_xh[(size_t)BB * SS * DM], g_xl[(size_t)BB * SS * DM];
__device__ __nv_bfloat16 g_wh[(size_t)3 * WSZ], g_wl[(size_t)3 * WSZ];
// Projected Q/K/V hi/lo, layout [b][h][s][d]  (Q pre-scaled by log2e)
__device__ __nv_bfloat16 g_qh[(size_t)BB * NH * SS * DH], g_ql[(size_t)BB * NH * SS * DH];
__device__ __nv_bfloat16 g_kh[(size_t)BB * NH * SS * DH], g_kl[(size_t)BB * NH * SS * DH];
__device__ __nv_bfloat16 g_vh[(size_t)BB * NH * SS * DH], g_vl[(size_t)BB * NH * SS * DH];

__device__ __forceinline__ void mma16816(float* c, const uint32_t* a, uint32_t b0,
                                         uint32_t b1) {
  asm volatile(
      "mma.sync.aligned.m16n8k16.row.col.f32.bf16.bf16.f32 "
      "{%0,%1,%2,%3}, {%4,%5,%6,%7}, {%8,%9}, {%0,%1,%2,%3};\n"
      : "+f"(c[0]), "+f"(c[1]), "+f"(c[2]), "+f"(c[3])
      : "r"(a[0]), "r"(a[1]), "r"(a[2]), "r"(a[3]), "r"(b0), "r"(b1));
}
__device__ __forceinline__ void ldsm_x4(uint32_t* r, const void* p) {
  uint32_t a = (uint32_t)__cvta_generic_to_shared(p);
  asm volatile("ldmatrix.sync.aligned.x4.m8n8.shared.b16 {%0,%1,%2,%3}, [%4];\n"
               : "=r"(r[0]), "=r"(r[1]), "=r"(r[2]), "=r"(r[3]) : "r"(a));
}
__device__ __forceinline__ void ldsm_x4_t(uint32_t* r, const void* p) {
  uint32_t a = (uint32_t)__cvta_generic_to_shared(p);
  asm volatile("ldmatrix.sync.aligned.x4.trans.m8n8.shared.b16 {%0,%1,%2,%3}, [%4];\n"
               : "=r"(r[0]), "=r"(r[1]), "=r"(r[2]), "=r"(r[3]) : "r"(a));
}
__device__ __forceinline__ void cp16(void* smem_dst, const void* gsrc) {
  uint32_t d = (uint32_t)__cvta_generic_to_shared(smem_dst);
  asm volatile("cp.async.cg.shared.global [%0], [%1], 16;\n" ::"r"(d), "l"(gsrc));
}
#define CP_COMMIT asm volatile("cp.async.commit_group;\n")
#define CP_WAIT0 asm volatile("cp.async.wait_group 0;\n")

__device__ __forceinline__ uint32_t pack_bf2(float x, float y) {
  __nv_bfloat162 t = __floats2bfloat162_rn(x, y);
  return *reinterpret_cast<uint32_t*>(&t);
}
__device__ __forceinline__ float ex2(float x) {
  float y;
  asm("ex2.approx.f32 %0, %1;" : "=f"(y) : "f"(x));
  return y;
}
// truncation split: hi-pair (exact bf16 = top 16 bits), lo = exact remainder
__device__ __forceinline__ void split_pair(float a, float b, uint32_t& hpair,
                                           uint32_t& lpair) {
  uint32_t ua = __float_as_uint(a), ub = __float_as_uint(b);
  hpair = __byte_perm(ua, ub, 0x7632);
  float la = a - __uint_as_float(ua & 0xffff0000u);
  float lb = b - __uint_as_float(ub & 0xffff0000u);
  lpair = pack_bf2(la, lb);
}

// ---------------------------------------------------------------------------
// fp32 -> bf16 hi/lo split, all 4 tensors in one launch.
// ---------------------------------------------------------------------------
__global__ __launch_bounds__(256) void split_kernel(
    const float* __restrict__ x, const float* __restrict__ Wq,
    const float* __restrict__ Wk, const float* __restrict__ Wv) {
  const int n4x = BB * SS * DM / 4, n4w = WSZ / 4;
  int i = blockIdx.x * 256 + threadIdx.x;
  const float* src;
  __nv_bfloat16 *hi, *lo;
  int j;
  if (i < n4x) {
    src = x; hi = g_xh; lo = g_xl; j = i;
  } else {
    int t = i - n4x;
    int w = t / n4w;
    j = t - w * n4w;
    src = (w == 0) ? Wq : (w == 1) ? Wk : Wv;
    hi = g_wh + (size_t)w * WSZ;
    lo = g_wl + (size_t)w * WSZ;
  }
  float4 v = ((const float4*)src)[j];
  uint2 H, L;
  split_pair(v.x, v.y, H.x, L.x);
  split_pair(v.z, v.w, H.y, L.y);
  ((uint2*)hi)[j] = H;
  ((uint2*)lo)[j] = L;
}

// ---------------------------------------------------------------------------
// Projection GEMM: M=4096, N=64 (per head), K=1024. bf16x3 emulated fp32.
// Block: BM=64, BN=64, BK=32, 4 warps. Single-sync cp.async pipeline.
// ---------------------------------------------------------------------------
__global__ __launch_bounds__(128, 4) void proj_kernel() {
  const int z = blockIdx.z, h = blockIdx.y, m0 = blockIdx.x * 64;
  const int tid = threadIdx.x, wid = tid >> 5, lane = tid & 31;
  const int gid = lane >> 2, tig = lane & 3;
  const int wm = (wid >> 1) * 32, wn = (wid & 1) * 32;

  __shared__ __align__(16) unsigned char sm[38912];
  char* smc = (char*)sm;

  const __nv_bfloat16* xg[2] = {g_xh, g_xl};
  const __nv_bfloat16* wg[2] = {g_wh + (size_t)z * WSZ + (size_t)h * DM * DH,
                                g_wl + (size_t)z * WSZ + (size_t)h * DM * DH};
  __nv_bfloat16* oh = (z == 0) ? g_qh : (z == 1) ? g_kh : g_vh;
  __nv_bfloat16* ol = (z == 0) ? g_ql : (z == 1) ? g_kl : g_vl;

  auto load_tile = [&](int k0, int st) {
#pragma unroll
    for (int i = 0; i < 4; i++) {
      int arr = i >> 1, q = tid + 128 * (i & 1);
      int r = q >> 2, c = q & 3;
      cp16(smc + st * 10240 + arr * 5120 + r * 80 + c * 16,
           xg[arr] + (size_t)(m0 + r) * DM + k0 + c * 8);
    }
#pragma unroll
    for (int i = 0; i < 4; i++) {
      int arr = i >> 1, q = tid + 128 * (i & 1);
      int r = q >> 3, c = q & 7;
      cp16(smc + 20480 + st * 9216 + arr * 4608 + r * 144 + c * 16,
           wg[arr] + (size_t)(k0 + r) * DH + c * 8);
    }
  };

  float acc[2][4][4] = {};

  load_tile(0, 0);
  CP_COMMIT;
#pragma unroll 2
  for (int it = 0; it < 32; it++) {
    CP_WAIT0;
    __syncthreads();
    if (it + 1 < 32) load_tile((it + 1) * 32, (it + 1) & 1);
    CP_COMMIT;
    const int st = it & 1;

    uint32_t ah[2][2][4], al[2][2][4];
#pragma unroll
    for (int mi = 0; mi < 2; mi++)
#pragma unroll
      for (int kk = 0; kk < 2; kk++) {
        const char* p = smc + st * 10240 + (wm + mi * 16 + (lane & 15)) * 80 +
                        (kk * 16 + (lane >> 4) * 8) * 2;
        ldsm_x4(ah[mi][kk], p);
        ldsm_x4(al[mi][kk], p + 5120);
      }
#pragma unroll
    for (int kk = 0; kk < 2; kk++)
#pragma unroll
      for (int njp = 0; njp < 2; njp++) {
        uint32_t bh[4], bl[4];
        const char* p = smc + 20480 + st * 9216 + (kk * 16 + (lane & 15)) * 144 +
                        (wn + njp * 16 + (lane >> 4) * 8) * 2;
        ldsm_x4_t(bh, p);
        ldsm_x4_t(bl, p + 4608);
#pragma unroll
        for (int mi = 0; mi < 2; mi++) {
          mma16816(acc[mi][2 * njp], ah[mi][kk], bh[0], bh[1]);
          mma16816(acc[mi][2 * njp], ah[mi][kk], bl[0], bl[1]);
          mma16816(acc[mi][2 * njp], al[mi][kk], bh[0], bh[1]);
          mma16816(acc[mi][2 * njp + 1], ah[mi][kk], bh[2], bh[3]);
          mma16816(acc[mi][2 * njp + 1], ah[mi][kk], bl[2], bl[3]);
          mma16816(acc[mi][2 * njp + 1], al[mi][kk], bh[2], bh[3]);
        }
      }
  }

  const float qs = (z == 0) ? LOG2E : 1.0f;  // fold log2e into Q
#pragma unroll
  for (int mi = 0; mi < 2; mi++)
#pragma unroll
    for (int nj = 0; nj < 4; nj++) {
      int col = wn + nj * 8 + 2 * tig;
#pragma unroll
      for (int rh = 0; rh < 2; rh++) {
        int r = m0 + wm + mi * 16 + gid + rh * 8;
        int b = r >> 11, si = r & (SS - 1);
        size_t base = (((size_t)(b * NH + h) * SS + si) * DH) + col;
        float c0 = acc[mi][nj][rh * 2] * qs, c1 = acc[mi][nj][rh * 2 + 1] * qs;
        uint32_t H, L;
        split_pair(c0, c1, H, L);
        *(uint32_t*)&oh[base] = H;
        *(uint32_t*)&ol[base] = L;
      }
    }
}

// ---------------------------------------------------------------------------
// Flash attention, bf16x3, UNNORMALIZED softmax (p = exp2(S'), log2e folded
// into Q). BM=64 q-rows, 4 warps. Bkv=32, 3-stage KV ring.
// Cross-iteration software pipeline: PV for tile jt-1 is interleaved with
// S for tile jt, giving each warp two independent HMMA streams.
// ---------------------------------------------------------------------------
__global__ __launch_bounds__(128, 3) void attn_kernel(float* __restrict__ out) {
  const int bh = blockIdx.y;
  const int b = bh >> 4, h = bh & 15;
  const int q0 = blockIdx.x * 64;
  const int tid = threadIdx.x, wid = tid >> 5, lane = tid & 31;
  const int gid = lane >> 2, tig = lane & 3;

  __shared__ __align__(16) unsigned char sm[55296];  // 3 stages x 18432
  char* smc = (char*)sm;

  const size_t kvbase = (size_t)bh * SS * DH;
  const __nv_bfloat16* kv_g[4] = {g_kh + kvbase, g_kl + kvbase, g_vh + kvbase,
                                  g_vl + kvbase};

  // ---- Q load + fragments (Q region overlaps stage 0 KV bufs) ----
  {
    const uint4* qh4 = (const uint4*)(g_qh + ((size_t)bh * SS + q0) * DH);
    const uint4* ql4 = (const uint4*)(g_ql + ((size_t)bh * SS + q0) * DH);
#pragma unroll
    for (int i = 0; i < 4; i++) {
      int q = tid + 128 * i;
      int r = q >> 3, c = q & 7;
      *(uint4*)(smc + r * 144 + c * 16) = qh4[r * 8 + c];
      *(uint4*)(smc + 9216 + r * 144 + c * 16) = ql4[r * 8 + c];
    }
  }
  __syncthreads();
  uint32_t qfh[4][4], qfl[4][4];
#pragma unroll
  for (int kk = 0; kk < 4; kk++) {
    const char* p = smc + (wid * 16 + (lane & 15)) * 144 + (kk * 16 + (lane >> 4) * 8) * 2;
    ldsm_x4(qfh[kk], p);
    ldsm_x4(qfl[kk], p + 9216);
  }
  __syncthreads();  // Q smem free; KV pipeline may overwrite

  float o[8][4] = {};
  float lr0 = 0.0f, lr1 = 0.0f;
  uint32_t pah[2][4], pal[2][4];  // P fragments carried from iter jt-1

  auto kvload = [&](int jt, int st) {
#pragma unroll
    for (int i = 0; i < 8; i++) {
      int arr = i >> 1;
      int q = tid + 128 * (i & 1);
      int r = q >> 3, c = q & 7;
      cp16(smc + st * 18432 + arr * 4608 + r * 144 + c * 16,
           kv_g[arr] + (size_t)(jt * 32 + r) * DH + c * 8);
    }
  };

  kvload(0, 0);
  CP_COMMIT;
  for (int jt = 0; jt < SS / 32; jt++) {
    CP_WAIT0;         // KV tile jt resident
    __syncthreads();  // all threads past reads of tile jt-2 (overwrite target)
    if (jt + 1 < SS / 32) {
      int st = (jt + 1) % 3;
      kvload(jt + 1, st);
    }
    CP_COMMIT;
    const char* kb = smc + (jt % 3) * 18432;              // K of tile jt
    const char* vb = smc + ((jt + 2) % 3) * 18432 + 9216; // V of tile jt-1

    // ---- interleaved: S' MMAs (tile jt) + PV MMAs (tile jt-1) ----
    float s[4][4] = {};
#pragma unroll
    for (int nj = 0; nj < 4; nj++) {
      uint32_t kh[8], kl[8];
      const char* pr = kb + (nj * 8 + (lane & 7)) * 144 + ((lane >> 3) * 8) * 2;
      ldsm_x4(kh, pr);
      ldsm_x4(kh + 4, pr + 64);
      ldsm_x4(kl, pr + 4608);
      ldsm_x4(kl + 4, pr + 4608 + 64);
#pragma unroll
      for (int kk = 0; kk < 4; kk++) {
        mma16816(s[nj], qfh[kk], kh[2 * kk], kh[2 * kk + 1]);
        mma16816(s[nj], qfh[kk], kl[2 * kk], kl[2 * kk + 1]);
        mma16816(s[nj], qfl[kk], kh[2 * kk], kh[2 * kk + 1]);
      }
      if (jt > 0) {  // PV chains for o[2nj], o[2nj+1] using carried P
#pragma unroll
        for (int kk = 0; kk < 2; kk++) {
          uint32_t vh[4], vl[4];
          const char* pv =
              vb + (kk * 16 + (lane & 15)) * 144 + (nj * 16 + (lane >> 4) * 8) * 2;
          ldsm_x4_t(vh, pv);
          ldsm_x4_t(vl, pv + 4608);
          mma16816(o[2 * nj], pah[kk], vh[0], vh[1]);
          mma16816(o[2 * nj], pah[kk], vl[0], vl[1]);
          mma16816(o[2 * nj], pal[kk], vh[0], vh[1]);
          mma16816(o[2 * nj + 1], pah[kk], vh[2], vh[3]);
          mma16816(o[2 * nj + 1], pah[kk], vl[2], vl[3]);
          mma16816(o[2 * nj + 1], pal[kk], vh[2], vh[3]);
        }
      }
    }

    // ---- p = 2^(S'), row sums, repack into carried P fragments ----
#pragma unroll
    for (int nj = 0; nj < 4; nj++) {
      s[nj][0] = ex2(s[nj][0]);
      s[nj][1] = ex2(s[nj][1]);
      s[nj][2] = ex2(s[nj][2]);
      s[nj][3] = ex2(s[nj][3]);
      lr0 += s[nj][0] + s[nj][1];
      lr1 += s[nj][2] + s[nj][3];
    }
#pragma unroll
    for (int kk = 0; kk < 2; kk++) {
      int j0 = 2 * kk, j1 = 2 * kk + 1;
      split_pair(s[j0][0], s[j0][1], pah[kk][0], pal[kk][0]);
      split_pair(s[j0][2], s[j0][3], pah[kk][1], pal[kk][1]);
      split_pair(s[j1][0], s[j1][1], pah[kk][2], pal[kk][2]);
      split_pair(s[j1][2], s[j1][3], pah[kk][3], pal[kk][3]);
    }
  }

  // ---- drain: PV for the last tile (stage (SS/32-1)%3) ----
  {
    const char* vb = smc + ((SS / 32 - 1) % 3) * 18432 + 9216;
#pragma unroll
    for (int nj = 0; nj < 4; nj++) {
#pragma unroll
      for (int kk = 0; kk < 2; kk++) {
        uint32_t vh[4], vl[4];
        const char* pv =
            vb + (kk * 16 + (lane & 15)) * 144 + (nj * 16 + (lane >> 4) * 8) * 2;
        ldsm_x4_t(vh, pv);
        ldsm_x4_t(vl, pv + 4608);
        mma16816(o[2 * nj], pah[kk], vh[0], vh[1]);
        mma16816(o[2 * nj], pah[kk], vl[0], vl[1]);
        mma16816(o[2 * nj], pal[kk], vh[0], vh[1]);
        mma16816(o[2 * nj + 1], pah[kk], vh[2], vh[3]);
        mma16816(o[2 * nj + 1], pah[kk], vl[2], vl[3]);
        mma16816(o[2 * nj + 1], pal[kk], vh[2], vh[3]);
      }
    }
  }

  // ---- final row-sum reduction across the 4-lane groups ----
#pragma unroll
  for (int d = 1; d <= 2; d <<= 1) {
    lr0 += __shfl_xor_sync(0xffffffffu, lr0, d);
    lr1 += __shfl_xor_sync(0xffffffffu, lr1, d);
  }
  const float inv0 = 1.0f / lr0, inv1 = 1.0f / lr1;
  const int r0g = q0 + wid * 16 + gid;
#pragma unroll
  for (int nj = 0; nj < 8; nj++) {
    int col = h * DH + nj * 8 + 2 * tig;
    float2 v0 = make_float2(o[nj][0] * inv0, o[nj][1] * inv0);
    float2 v1 = make_float2(o[nj][2] * inv1, o[nj][3] * inv1);
    *(float2*)&out[((size_t)b * SS + r0g) * (NH * DH) + col] = v0;
    *(float2*)&out[((size_t)b * SS + r0g + 8) * (NH * DH) + col] = v1;
  }
}

extern "C" void kernel_launch(void* const* d_in, const int* in_sizes, int n_in,
                              void* d_out, int out_size) {
  const float* x = (const float*)d_in[0];
  const float* Wq = (const float*)d_in[1];
  const float* Wk = (const float*)d_in[2];
  const float* Wv = (const float*)d_in[3];
  float* out = (float*)d_out;

  const int n4 = BB * SS * DM / 4 + 3 * (WSZ / 4);
  split_kernel<<<(n4 + 255) / 256, 256>>>(x, Wq, Wk, Wv);
  proj_kernel<<<dim3(64, NH, 3), 128>>>();
  attn_kernel<<<dim3(SS / 64, BB * NH), 128>>>(out);
}

// round 10
// speedup vs baseline: 1.0637x; 1.0637x over previous
#include <cuda_runtime.h>
#include <cuda_bf16.h>
#include <stdint.h>

#define BB 2
#define SS 2048
#define DM 1024
#define NH 16
#define DH 64
#define WSZ (NH * DM * DH)
#define LOG2E 1.4426950408889634f

// Pre-split inputs (hi/lo bf16)
__device__ __nv_bfloat16 g_xh[(size_t)BB * SS * DM], g_xl[(size_t)BB * SS * DM];
__device__ __nv_bfloat16 g_wh[(size_t)3 * WSZ], g_wl[(size_t)3 * WSZ];
// Projected Q/K/V hi/lo, layout [b][h][s][d]  (Q pre-scaled by log2e)
__device__ __nv_bfloat16 g_qh[(size_t)BB * NH * SS * DH], g_ql[(size_t)BB * NH * SS * DH];
__device__ __nv_bfloat16 g_kh[(size_t)BB * NH * SS * DH], g_kl[(size_t)BB * NH * SS * DH];
__device__ __nv_bfloat16 g_vh[(size_t)BB * NH * SS * DH], g_vl[(size_t)BB * NH * SS * DH];

__device__ __forceinline__ void mma16816(float* c, const uint32_t* a, uint32_t b0,
                                         uint32_t b1) {
  asm volatile(
      "mma.sync.aligned.m16n8k16.row.col.f32.bf16.bf16.f32 "
      "{%0,%1,%2,%3}, {%4,%5,%6,%7}, {%8,%9}, {%0,%1,%2,%3};\n"
      : "+f"(c[0]), "+f"(c[1]), "+f"(c[2]), "+f"(c[3])
      : "r"(a[0]), "r"(a[1]), "r"(a[2]), "r"(a[3]), "r"(b0), "r"(b1));
}
__device__ __forceinline__ void ldsm_x4(uint32_t* r, const void* p) {
  uint32_t a = (uint32_t)__cvta_generic_to_shared(p);
  asm volatile("ldmatrix.sync.aligned.x4.m8n8.shared.b16 {%0,%1,%2,%3}, [%4];\n"
               : "=r"(r[0]), "=r"(r[1]), "=r"(r[2]), "=r"(r[3]) : "r"(a));
}
__device__ __forceinline__ void ldsm_x4_t(uint32_t* r, const void* p) {
  uint32_t a = (uint32_t)__cvta_generic_to_shared(p);
  asm volatile("ldmatrix.sync.aligned.x4.trans.m8n8.shared.b16 {%0,%1,%2,%3}, [%4];\n"
               : "=r"(r[0]), "=r"(r[1]), "=r"(r[2]), "=r"(r[3]) : "r"(a));
}
__device__ __forceinline__ void cp16(void* smem_dst, const void* gsrc) {
  uint32_t d = (uint32_t)__cvta_generic_to_shared(smem_dst);
  asm volatile("cp.async.cg.shared.global [%0], [%1], 16;\n" ::"r"(d), "l"(gsrc));
}
#define CP_COMMIT asm volatile("cp.async.commit_group;\n")
#define CP_WAIT0 asm volatile("cp.async.wait_group 0;\n")

__device__ __forceinline__ uint32_t pack_bf2(float x, float y) {
  __nv_bfloat162 t = __floats2bfloat162_rn(x, y);
  return *reinterpret_cast<uint32_t*>(&t);
}
__device__ __forceinline__ float ex2(float x) {
  float y;
  asm("ex2.approx.f32 %0, %1;" : "=f"(y) : "f"(x));
  return y;
}
// truncation split: hi-pair (exact bf16 = top 16 bits), lo = exact remainder
__device__ __forceinline__ void split_pair(float a, float b, uint32_t& hpair,
                                           uint32_t& lpair) {
  uint32_t ua = __float_as_uint(a), ub = __float_as_uint(b);
  hpair = __byte_perm(ua, ub, 0x7632);
  float la = a - __uint_as_float(ua & 0xffff0000u);
  float lb = b - __uint_as_float(ub & 0xffff0000u);
  lpair = pack_bf2(la, lb);
}

// ---------------------------------------------------------------------------
// fp32 -> bf16 hi/lo split, all 4 tensors in one launch.
// ---------------------------------------------------------------------------
__global__ __launch_bounds__(256) void split_kernel(
    const float* __restrict__ x, const float* __restrict__ Wq,
    const float* __restrict__ Wk, const float* __restrict__ Wv) {
  const int n4x = BB * SS * DM / 4, n4w = WSZ / 4;
  int i = blockIdx.x * 256 + threadIdx.x;
  const float* src;
  __nv_bfloat16 *hi, *lo;
  int j;
  if (i < n4x) {
    src = x; hi = g_xh; lo = g_xl; j = i;
  } else {
    int t = i - n4x;
    int w = t / n4w;
    j = t - w * n4w;
    src = (w == 0) ? Wq : (w == 1) ? Wk : Wv;
    hi = g_wh + (size_t)w * WSZ;
    lo = g_wl + (size_t)w * WSZ;
  }
  float4 v = ((const float4*)src)[j];
  uint2 H, L;
  split_pair(v.x, v.y, H.x, L.x);
  split_pair(v.z, v.w, H.y, L.y);
  ((uint2*)hi)[j] = H;
  ((uint2*)lo)[j] = L;
}

// ---------------------------------------------------------------------------
// Projection GEMM: M=4096, N=64 (per head), K=1024. bf16x3 emulated fp32.
// Block: BM=128, BN=64, BK=16, 4 warps (2m x 2n, warp=64x32).
// Halves W L2 traffic vs BM=64. Static smem 33792B, single-sync pipeline.
// Uniform epilogue: all z write [b][h][s][d] (Q scaled by log2e).
// ---------------------------------------------------------------------------
__global__ __launch_bounds__(128, 4) void proj_kernel() {
  const int z = blockIdx.z, h = blockIdx.y, m0 = blockIdx.x * 128;
  const int tid = threadIdx.x, wid = tid >> 5, lane = tid & 31;
  const int gid = lane >> 2, tig = lane & 3;
  const int wm = (wid >> 1) * 64, wn = (wid & 1) * 32;

  // X: [st][arr][128 rows][48B] = 24576; W at 24576: [st][arr][16][144B] = 9216
  __shared__ __align__(16) unsigned char sm[33792];
  char* smc = (char*)sm;

  const __nv_bfloat16* xg[2] = {g_xh, g_xl};
  const __nv_bfloat16* wg[2] = {g_wh + (size_t)z * WSZ + (size_t)h * DM * DH,
                                g_wl + (size_t)z * WSZ + (size_t)h * DM * DH};
  __nv_bfloat16* oh = (z == 0) ? g_qh : (z == 1) ? g_kh : g_vh;
  __nv_bfloat16* ol = (z == 0) ? g_ql : (z == 1) ? g_kl : g_vl;

  auto load_tile = [&](int k0, int st) {
#pragma unroll
    for (int i = 0; i < 4; i++) {  // X: 2arr x 128 rows x 2 quads
      int q = tid + 128 * i;
      int arr = q >> 8, r = (q >> 1) & 127, c = q & 1;
      cp16(smc + st * 12288 + arr * 6144 + r * 48 + c * 16,
           xg[arr] + (size_t)(m0 + r) * DM + k0 + c * 8);
    }
#pragma unroll
    for (int i = 0; i < 2; i++) {  // W: 2arr x 16 rows x 8 quads
      int q = tid + 128 * i;
      int arr = q >> 7, r = (q >> 3) & 15, c = q & 7;
      cp16(smc + 24576 + st * 4608 + arr * 2304 + r * 144 + c * 16,
           wg[arr] + (size_t)(k0 + r) * DH + c * 8);
    }
  };

  float acc[4][4][4] = {};

  load_tile(0, 0);
  CP_COMMIT;
#pragma unroll 2
  for (int it = 0; it < 64; it++) {
    CP_WAIT0;
    __syncthreads();
    if (it + 1 < 64) load_tile((it + 1) * 16, (it + 1) & 1);
    CP_COMMIT;
    const int st = it & 1;

    uint32_t ah[4][4], al[4][4];
#pragma unroll
    for (int mi = 0; mi < 4; mi++) {
      const char* p =
          smc + st * 12288 + (wm + mi * 16 + (lane & 15)) * 48 + ((lane >> 4) * 8) * 2;
      ldsm_x4(ah[mi], p);
      ldsm_x4(al[mi], p + 6144);
    }
#pragma unroll
    for (int njp = 0; njp < 2; njp++) {
      uint32_t bh[4], bl[4];
      const char* p = smc + 24576 + st * 4608 + (lane & 15) * 144 +
                      (wn + njp * 16 + (lane >> 4) * 8) * 2;
      ldsm_x4_t(bh, p);
      ldsm_x4_t(bl, p + 2304);
#pragma unroll
      for (int mi = 0; mi < 4; mi++) {
        mma16816(acc[mi][2 * njp], ah[mi], bh[0], bh[1]);
        mma16816(acc[mi][2 * njp], ah[mi], bl[0], bl[1]);
        mma16816(acc[mi][2 * njp], al[mi], bh[0], bh[1]);
        mma16816(acc[mi][2 * njp + 1], ah[mi], bh[2], bh[3]);
        mma16816(acc[mi][2 * njp + 1], ah[mi], bl[2], bl[3]);
        mma16816(acc[mi][2 * njp + 1], al[mi], bh[2], bh[3]);
      }
    }
  }

  const float qs = (z == 0) ? LOG2E : 1.0f;  // fold log2e into Q
#pragma unroll
  for (int mi = 0; mi < 4; mi++)
#pragma unroll
    for (int nj = 0; nj < 4; nj++) {
      int col = wn + nj * 8 + 2 * tig;
#pragma unroll
      for (int rh = 0; rh < 2; rh++) {
        int r = m0 + wm + mi * 16 + gid + rh * 8;
        int b = r >> 11, si = r & (SS - 1);
        size_t base = (((size_t)(b * NH + h) * SS + si) * DH) + col;
        float c0 = acc[mi][nj][rh * 2] * qs, c1 = acc[mi][nj][rh * 2 + 1] * qs;
        uint32_t H, L;
        split_pair(c0, c1, H, L);
        *(uint32_t*)&oh[base] = H;
        *(uint32_t*)&ol[base] = L;
      }
    }
}

// ---------------------------------------------------------------------------
// Flash attention, bf16x3, UNNORMALIZED softmax (p = exp2(S'), log2e folded
// into Q; scores bounded ~|17| so fp32 range suffices). Single sync per iter.
// Dual QK accumulators (s = hi*hi, s2 = cross terms) halve the serial HMMA
// dependency depth per C-register chain (12 -> 8/4).
// ---------------------------------------------------------------------------
__global__ __launch_bounds__(128, 3) void attn_kernel(float* __restrict__ out) {
  const int bh = blockIdx.y;
  const int b = bh >> 4, h = bh & 15;
  const int q0 = blockIdx.x * 64;
  const int tid = threadIdx.x, wid = tid >> 5, lane = tid & 31;
  const int gid = lane >> 2, tig = lane & 3;

  __shared__ __align__(16) unsigned char sm[36864];
  char* smc = (char*)sm;

  const size_t kvbase = (size_t)bh * SS * DH;
  const __nv_bfloat16* kv_g[4] = {g_kh + kvbase, g_kl + kvbase, g_vh + kvbase,
                                  g_vl + kvbase};

  // ---- Q load + fragments (Q region overlaps KV stage bufs) ----
  {
    const uint4* qh4 = (const uint4*)(g_qh + ((size_t)bh * SS + q0) * DH);
    const uint4* ql4 = (const uint4*)(g_ql + ((size_t)bh * SS + q0) * DH);
#pragma unroll
    for (int i = 0; i < 4; i++) {
      int q = tid + 128 * i;
      int r = q >> 3, c = q & 7;
      *(uint4*)(smc + r * 144 + c * 16) = qh4[r * 8 + c];
      *(uint4*)(smc + 9216 + r * 144 + c * 16) = ql4[r * 8 + c];
    }
  }
  __syncthreads();
  uint32_t qfh[4][4], qfl[4][4];
#pragma unroll
  for (int kk = 0; kk < 4; kk++) {
    const char* p = smc + (wid * 16 + (lane & 15)) * 144 + (kk * 16 + (lane >> 4) * 8) * 2;
    ldsm_x4(qfh[kk], p);
    ldsm_x4(qfl[kk], p + 9216);
  }
  __syncthreads();  // Q smem free; KV pipeline may overwrite

  float o[8][4] = {};
  float lr0 = 0.0f, lr1 = 0.0f;

  auto kvload = [&](int jt, int st) {
#pragma unroll
    for (int i = 0; i < 8; i++) {
      int arr = i >> 1;
      int q = tid + 128 * (i & 1);
      int r = q >> 3, c = q & 7;
      cp16(smc + st * 18432 + arr * 4608 + r * 144 + c * 16,
           kv_g[arr] + (size_t)(jt * 32 + r) * DH + c * 8);
    }
  };

  kvload(0, 0);
  CP_COMMIT;
#pragma unroll 2
  for (int jt = 0; jt < SS / 32; jt++) {
    CP_WAIT0;
    __syncthreads();
    if (jt + 1 < SS / 32) kvload(jt + 1, (jt + 1) & 1);
    CP_COMMIT;
    const char* base = smc + (jt & 1) * 18432;

    // ---- S' = (log2e*Q) K^T, split across two accumulator sets ----
    float s[4][4] = {};
    float s2[4][4] = {};
#pragma unroll
    for (int nj = 0; nj < 4; nj++) {
      uint32_t kh[8], kl[8];
      const char* pr = base + (nj * 8 + (lane & 7)) * 144 + ((lane >> 3) * 8) * 2;
      ldsm_x4(kh, pr);
      ldsm_x4(kh + 4, pr + 64);
      ldsm_x4(kl, pr + 4608);
      ldsm_x4(kl + 4, pr + 4608 + 64);
#pragma unroll
      for (int kk = 0; kk < 4; kk++) {
        mma16816(s[nj], qfh[kk], kh[2 * kk], kh[2 * kk + 1]);   // hi*hi (depth 4)
        mma16816(s2[nj], qfh[kk], kl[2 * kk], kl[2 * kk + 1]);  // hi*lo
        mma16816(s2[nj], qfl[kk], kh[2 * kk], kh[2 * kk + 1]);  // lo*hi (depth 8)
      }
    }

    // ---- p = 2^(s + s2), accumulate row sums locally ----
#pragma unroll
    for (int nj = 0; nj < 4; nj++) {
      s[nj][0] = ex2(s[nj][0] + s2[nj][0]);
      s[nj][1] = ex2(s[nj][1] + s2[nj][1]);
      s[nj][2] = ex2(s[nj][2] + s2[nj][2]);
      s[nj][3] = ex2(s[nj][3] + s2[nj][3]);
      lr0 += s[nj][0] + s[nj][1];
      lr1 += s[nj][2] + s[nj][3];
    }

    // ---- repack P (C-frag -> A-frag, lane-local), truncation hi/lo ----
    uint32_t pah[2][4], pal[2][4];
#pragma unroll
    for (int kk = 0; kk < 2; kk++) {
      int j0 = 2 * kk, j1 = 2 * kk + 1;
      split_pair(s[j0][0], s[j0][1], pah[kk][0], pal[kk][0]);
      split_pair(s[j0][2], s[j0][3], pah[kk][1], pal[kk][1]);
      split_pair(s[j1][0], s[j1][1], pah[kk][2], pal[kk][2]);
      split_pair(s[j1][2], s[j1][3], pah[kk][3], pal[kk][3]);
    }

    // ---- O += P V ----
    const char* vb = base + 2 * 4608;
#pragma unroll
    for (int njp = 0; njp < 4; njp++) {
#pragma unroll
      for (int kk = 0; kk < 2; kk++) {
        uint32_t vh[4], vl[4];
        const char* pv = vb + (kk * 16 + (lane & 15)) * 144 + (njp * 16 + (lane >> 4) * 8) * 2;
        ldsm_x4_t(vh, pv);
        ldsm_x4_t(vl, pv + 4608);
        mma16816(o[2 * njp], pah[kk], vh[0], vh[1]);
        mma16816(o[2 * njp], pah[kk], vl[0], vl[1]);
        mma16816(o[2 * njp], pal[kk], vh[0], vh[1]);
        mma16816(o[2 * njp + 1], pah[kk], vh[2], vh[3]);
        mma16816(o[2 * njp + 1], pah[kk], vl[2], vl[3]);
        mma16816(o[2 * njp + 1], pal[kk], vh[2], vh[3]);
      }
    }
  }

  // ---- final row-sum reduction across the 4-lane groups ----
#pragma unroll
  for (int d = 1; d <= 2; d <<= 1) {
    lr0 += __shfl_xor_sync(0xffffffffu, lr0, d);
    lr1 += __shfl_xor_sync(0xffffffffu, lr1, d);
  }
  const float inv0 = 1.0f / lr0, inv1 = 1.0f / lr1;
  const int r0g = q0 + wid * 16 + gid;
#pragma unroll
  for (int nj = 0; nj < 8; nj++) {
    int col = h * DH + nj * 8 + 2 * tig;
    float2 v0 = make_float2(o[nj][0] * inv0, o[nj][1] * inv0);
    float2 v1 = make_float2(o[nj][2] * inv1, o[nj][3] * inv1);
    *(float2*)&out[((size_t)b * SS + r0g) * (NH * DH) + col] = v0;
    *(float2*)&out[((size_t)b * SS + r0g + 8) * (NH * DH) + col] = v1;
  }
}

extern "C" void kernel_launch(void* const* d_in, const int* in_sizes, int n_in,
                              void* d_out, int out_size) {
  const float* x = (const float*)d_in[0];
  const float* Wq = (const float*)d_in[1];
  const float* Wk = (const float*)d_in[2];
  const float* Wv = (const float*)d_in[3];
  float* out = (float*)d_out;

  const int n4 = BB * SS * DM / 4 + 3 * (WSZ / 4);
  split_kernel<<<(n4 + 255) / 256, 256>>>(x, Wq, Wk, Wv);
  proj_kernel<<<dim3(32, NH, 3), 128>>>();
  attn_kernel<<<dim3(SS / 64, BB * NH), 128>>>(out);
}

// round 11
// speedup vs baseline: 1.1312x; 1.0635x over previous
#include <cuda_runtime.h>
#include <cuda_bf16.h>
#include <stdint.h>

#define BB 2
#define SS 2048
#define DM 1024
#define NH 16
#define DH 64
#define WSZ (NH * DM * DH)
#define LOG2E 1.4426950408889634f

// Pre-split inputs (hi/lo bf16)
__device__ __nv_bfloat16 g_xh[(size_t)BB * SS * DM], g_xl[(size_t)BB * SS * DM];
__device__ __nv_bfloat16 g_wh[(size_t)3 * WSZ], g_wl[(size_t)3 * WSZ];
// Projected Q/K/V hi/lo, layout [b][h][s][d]  (Q pre-scaled by log2e)
__device__ __nv_bfloat16 g_qh[(size_t)BB * NH * SS * DH], g_ql[(size_t)BB * NH * SS * DH];
__device__ __nv_bfloat16 g_kh[(size_t)BB * NH * SS * DH], g_kl[(size_t)BB * NH * SS * DH];
__device__ __nv_bfloat16 g_vh[(size_t)BB * NH * SS * DH], g_vl[(size_t)BB * NH * SS * DH];

__device__ __forceinline__ void mma16816(float* c, const uint32_t* a, uint32_t b0,
                                         uint32_t b1) {
  asm volatile(
      "mma.sync.aligned.m16n8k16.row.col.f32.bf16.bf16.f32 "
      "{%0,%1,%2,%3}, {%4,%5,%6,%7}, {%8,%9}, {%0,%1,%2,%3};\n"
      : "+f"(c[0]), "+f"(c[1]), "+f"(c[2]), "+f"(c[3])
      : "r"(a[0]), "r"(a[1]), "r"(a[2]), "r"(a[3]), "r"(b0), "r"(b1));
}
__device__ __forceinline__ void ldsm_x4(uint32_t* r, const void* p) {
  uint32_t a = (uint32_t)__cvta_generic_to_shared(p);
  asm volatile("ldmatrix.sync.aligned.x4.m8n8.shared.b16 {%0,%1,%2,%3}, [%4];\n"
               : "=r"(r[0]), "=r"(r[1]), "=r"(r[2]), "=r"(r[3]) : "r"(a));
}
__device__ __forceinline__ void ldsm_x4_t(uint32_t* r, const void* p) {
  uint32_t a = (uint32_t)__cvta_generic_to_shared(p);
  asm volatile("ldmatrix.sync.aligned.x4.trans.m8n8.shared.b16 {%0,%1,%2,%3}, [%4];\n"
               : "=r"(r[0]), "=r"(r[1]), "=r"(r[2]), "=r"(r[3]) : "r"(a));
}
__device__ __forceinline__ void cp16(void* smem_dst, const void* gsrc) {
  uint32_t d = (uint32_t)__cvta_generic_to_shared(smem_dst);
  asm volatile("cp.async.cg.shared.global [%0], [%1], 16;\n" ::"r"(d), "l"(gsrc));
}
#define CP_COMMIT asm volatile("cp.async.commit_group;\n")
#define CP_WAIT0 asm volatile("cp.async.wait_group 0;\n")

__device__ __forceinline__ uint32_t pack_bf2(float x, float y) {
  __nv_bfloat162 t = __floats2bfloat162_rn(x, y);
  return *reinterpret_cast<uint32_t*>(&t);
}
__device__ __forceinline__ float ex2(float x) {
  float y;
  asm("ex2.approx.f32 %0, %1;" : "=f"(y) : "f"(x));
  return y;
}
// truncation split: hi-pair (exact bf16 = top 16 bits), lo = exact remainder
__device__ __forceinline__ void split_pair(float a, float b, uint32_t& hpair,
                                           uint32_t& lpair) {
  uint32_t ua = __float_as_uint(a), ub = __float_as_uint(b);
  hpair = __byte_perm(ua, ub, 0x7632);
  float la = a - __uint_as_float(ua & 0xffff0000u);
  float lb = b - __uint_as_float(ub & 0xffff0000u);
  lpair = pack_bf2(la, lb);
}

// ---------------------------------------------------------------------------
// fp32 -> bf16 hi/lo split, all 4 tensors in one launch.
// ---------------------------------------------------------------------------
__global__ __launch_bounds__(256) void split_kernel(
    const float* __restrict__ x, const float* __restrict__ Wq,
    const float* __restrict__ Wk, const float* __restrict__ Wv) {
  const int n4x = BB * SS * DM / 4, n4w = WSZ / 4;
  int i = blockIdx.x * 256 + threadIdx.x;
  const float* src;
  __nv_bfloat16 *hi, *lo;
  int j;
  if (i < n4x) {
    src = x; hi = g_xh; lo = g_xl; j = i;
  } else {
    int t = i - n4x;
    int w = t / n4w;
    j = t - w * n4w;
    src = (w == 0) ? Wq : (w == 1) ? Wk : Wv;
    hi = g_wh + (size_t)w * WSZ;
    lo = g_wl + (size_t)w * WSZ;
  }
  float4 v = ((const float4*)src)[j];
  uint2 H, L;
  split_pair(v.x, v.y, H.x, L.x);
  split_pair(v.z, v.w, H.y, L.y);
  ((uint2*)hi)[j] = H;
  ((uint2*)lo)[j] = L;
}

// ---------------------------------------------------------------------------
// Projection GEMM, ALL THREE z per block: X tile loaded once, used for
// Q,K,V GEMMs -> X L2 traffic /3. M=4096 (64 m-tiles), per-z N=64, K=1024.
// BM=64, BK=16, 4 warps (2m x 2n). 2-stage cp.async, single sync per iter.
// smem: X[2 st][2 arr][64 r][48B] = 12288; W at 12288: [2 st][3 z][2 arr][16][144B]
// = 27648. Total 39936B static.
// ---------------------------------------------------------------------------
__global__ __launch_bounds__(128, 3) void proj_kernel() {
  const int h = blockIdx.y, m0 = blockIdx.x * 64;
  const int tid = threadIdx.x, wid = tid >> 5, lane = tid & 31;
  const int gid = lane >> 2, tig = lane & 3;
  const int wm = (wid >> 1) * 32, wn = (wid & 1) * 32;

  __shared__ __align__(16) unsigned char sm[39936];
  char* smc = (char*)sm;

  const __nv_bfloat16* xg[2] = {g_xh, g_xl};
  const __nv_bfloat16* wg[3][2] = {
      {g_wh + (size_t)h * DM * DH, g_wl + (size_t)h * DM * DH},
      {g_wh + WSZ + (size_t)h * DM * DH, g_wl + WSZ + (size_t)h * DM * DH},
      {g_wh + 2 * (size_t)WSZ + (size_t)h * DM * DH,
       g_wl + 2 * (size_t)WSZ + (size_t)h * DM * DH}};
  __nv_bfloat16* oh[3] = {g_qh, g_kh, g_vh};
  __nv_bfloat16* ol[3] = {g_ql, g_kl, g_vl};

  auto load_tile = [&](int k0, int st) {
#pragma unroll
    for (int i = 0; i < 2; i++) {  // X: 256 quads (2 arr x 64 rows x 2)
      int q = tid + 128 * i;
      int arr = q >> 7, r = (q >> 1) & 63, c = q & 1;
      cp16(smc + st * 6144 + arr * 3072 + r * 48 + c * 16,
           xg[arr] + (size_t)(m0 + r) * DM + k0 + c * 8);
    }
#pragma unroll
    for (int i = 0; i < 6; i++) {  // W: 768 quads (3 z x 2 arr x 16 rows x 8)
      int q = tid + 128 * i;
      int zarr = q >> 7, z = zarr >> 1, arr = zarr & 1;
      int r = (q >> 3) & 15, c = q & 7;
      cp16(smc + 12288 + st * 13824 + z * 4608 + arr * 2304 + r * 144 + c * 16,
           wg[z][arr] + (size_t)(k0 + r) * DH + c * 8);
    }
  };

  float acc[3][2][4][4] = {};

  load_tile(0, 0);
  CP_COMMIT;
  for (int it = 0; it < 64; it++) {
    CP_WAIT0;
    __syncthreads();
    if (it + 1 < 64) load_tile((it + 1) * 16, (it + 1) & 1);
    CP_COMMIT;
    const int st = it & 1;

    uint32_t ah[2][4], al[2][4];
#pragma unroll
    for (int mi = 0; mi < 2; mi++) {
      const char* p = smc + st * 6144 + (wm + mi * 16 + (lane & 15)) * 48 +
                      ((lane >> 4) * 8) * 2;
      ldsm_x4(ah[mi], p);
      ldsm_x4(al[mi], p + 3072);
    }
#pragma unroll
    for (int z = 0; z < 3; z++) {
#pragma unroll
      for (int njp = 0; njp < 2; njp++) {
        uint32_t bh[4], bl[4];
        const char* p = smc + 12288 + st * 13824 + z * 4608 + (lane & 15) * 144 +
                        (wn + njp * 16 + (lane >> 4) * 8) * 2;
        ldsm_x4_t(bh, p);
        ldsm_x4_t(bl, p + 2304);
#pragma unroll
        for (int mi = 0; mi < 2; mi++) {
          mma16816(acc[z][mi][2 * njp], ah[mi], bh[0], bh[1]);
          mma16816(acc[z][mi][2 * njp], ah[mi], bl[0], bl[1]);
          mma16816(acc[z][mi][2 * njp], al[mi], bh[0], bh[1]);
          mma16816(acc[z][mi][2 * njp + 1], ah[mi], bh[2], bh[3]);
          mma16816(acc[z][mi][2 * njp + 1], ah[mi], bl[2], bl[3]);
          mma16816(acc[z][mi][2 * njp + 1], al[mi], bh[2], bh[3]);
        }
      }
    }
  }

#pragma unroll
  for (int z = 0; z < 3; z++) {
    const float qs = (z == 0) ? LOG2E : 1.0f;  // fold log2e into Q
#pragma unroll
    for (int mi = 0; mi < 2; mi++)
#pragma unroll
      for (int nj = 0; nj < 4; nj++) {
        int col = wn + nj * 8 + 2 * tig;
#pragma unroll
        for (int rh = 0; rh < 2; rh++) {
          int r = m0 + wm + mi * 16 + gid + rh * 8;
          int b = r >> 11, si = r & (SS - 1);
          size_t base = (((size_t)(b * NH + h) * SS + si) * DH) + col;
          float c0 = acc[z][mi][nj][rh * 2] * qs, c1 = acc[z][mi][nj][rh * 2 + 1] * qs;
          uint32_t H, L;
          split_pair(c0, c1, H, L);
          *(uint32_t*)&oh[z][base] = H;
          *(uint32_t*)&ol[z][base] = L;
        }
      }
  }
}

// ---------------------------------------------------------------------------
// Flash attention (EXACT R5 best config): bf16x3, UNNORMALIZED softmax
// (p = exp2(S'), log2e folded into Q; scores bounded ~|17|). BM=64, 4 warps,
// Bkv=32, 2-stage cp.async, single sync per iter.
// ---------------------------------------------------------------------------
__global__ __launch_bounds__(128, 4) void attn_kernel(float* __restrict__ out) {
  const int bh = blockIdx.y;
  const int b = bh >> 4, h = bh & 15;
  const int q0 = blockIdx.x * 64;
  const int tid = threadIdx.x, wid = tid >> 5, lane = tid & 31;
  const int gid = lane >> 2, tig = lane & 3;

  __shared__ __align__(16) unsigned char sm[36864];
  char* smc = (char*)sm;

  const size_t kvbase = (size_t)bh * SS * DH;
  const __nv_bfloat16* kv_g[4] = {g_kh + kvbase, g_kl + kvbase, g_vh + kvbase,
                                  g_vl + kvbase};

  // ---- Q load + fragments (Q region overlaps KV stage bufs) ----
  {
    const uint4* qh4 = (const uint4*)(g_qh + ((size_t)bh * SS + q0) * DH);
    const uint4* ql4 = (const uint4*)(g_ql + ((size_t)bh * SS + q0) * DH);
#pragma unroll
    for (int i = 0; i < 4; i++) {
      int q = tid + 128 * i;
      int r = q >> 3, c = q & 7;
      *(uint4*)(smc + r * 144 + c * 16) = qh4[r * 8 + c];
      *(uint4*)(smc + 9216 + r * 144 + c * 16) = ql4[r * 8 + c];
    }
  }
  __syncthreads();
  uint32_t qfh[4][4], qfl[4][4];
#pragma unroll
  for (int kk = 0; kk < 4; kk++) {
    const char* p = smc + (wid * 16 + (lane & 15)) * 144 + (kk * 16 + (lane >> 4) * 8) * 2;
    ldsm_x4(qfh[kk], p);
    ldsm_x4(qfl[kk], p + 9216);
  }
  __syncthreads();  // Q smem free; KV pipeline may overwrite

  float o[8][4] = {};
  float lr0 = 0.0f, lr1 = 0.0f;

  auto kvload = [&](int jt, int st) {
#pragma unroll
    for (int i = 0; i < 8; i++) {
      int arr = i >> 1;
      int q = tid + 128 * (i & 1);
      int r = q >> 3, c = q & 7;
      cp16(smc + st * 18432 + arr * 4608 + r * 144 + c * 16,
           kv_g[arr] + (size_t)(jt * 32 + r) * DH + c * 8);
    }
  };

  kvload(0, 0);
  CP_COMMIT;
#pragma unroll 2
  for (int jt = 0; jt < SS / 32; jt++) {
    CP_WAIT0;
    __syncthreads();
    if (jt + 1 < SS / 32) kvload(jt + 1, (jt + 1) & 1);
    CP_COMMIT;
    const char* base = smc + (jt & 1) * 18432;

    // ---- S' = (log2e*Q) K^T ----
    float s[4][4] = {};
#pragma unroll
    for (int nj = 0; nj < 4; nj++) {
      uint32_t kh[8], kl[8];
      const char* pr = base + (nj * 8 + (lane & 7)) * 144 + ((lane >> 3) * 8) * 2;
      ldsm_x4(kh, pr);
      ldsm_x4(kh + 4, pr + 64);
      ldsm_x4(kl, pr + 4608);
      ldsm_x4(kl + 4, pr + 4608 + 64);
#pragma unroll
      for (int kk = 0; kk < 4; kk++) {
        mma16816(s[nj], qfh[kk], kh[2 * kk], kh[2 * kk + 1]);
        mma16816(s[nj], qfh[kk], kl[2 * kk], kl[2 * kk + 1]);
        mma16816(s[nj], qfl[kk], kh[2 * kk], kh[2 * kk + 1]);
      }
    }

    // ---- p = 2^(S'), accumulate row sums locally ----
#pragma unroll
    for (int nj = 0; nj < 4; nj++) {
      s[nj][0] = ex2(s[nj][0]);
      s[nj][1] = ex2(s[nj][1]);
      s[nj][2] = ex2(s[nj][2]);
      s[nj][3] = ex2(s[nj][3]);
      lr0 += s[nj][0] + s[nj][1];
      lr1 += s[nj][2] + s[nj][3];
    }

    // ---- repack P (C-frag -> A-frag, lane-local), truncation hi/lo ----
    uint32_t pah[2][4], pal[2][4];
#pragma unroll
    for (int kk = 0; kk < 2; kk++) {
      int j0 = 2 * kk, j1 = 2 * kk + 1;
      split_pair(s[j0][0], s[j0][1], pah[kk][0], pal[kk][0]);
      split_pair(s[j0][2], s[j0][3], pah[kk][1], pal[kk][1]);
      split_pair(s[j1][0], s[j1][1], pah[kk][2], pal[kk][2]);
      split_pair(s[j1][2], s[j1][3], pah[kk][3], pal[kk][3]);
    }

    // ---- O += P V ----
    const char* vb = base + 2 * 4608;
#pragma unroll
    for (int njp = 0; njp < 4; njp++) {
#pragma unroll
      for (int kk = 0; kk < 2; kk++) {
        uint32_t vh[4], vl[4];
        const char* pv = vb + (kk * 16 + (lane & 15)) * 144 + (njp * 16 + (lane >> 4) * 8) * 2;
        ldsm_x4_t(vh, pv);
        ldsm_x4_t(vl, pv + 4608);
        mma16816(o[2 * njp], pah[kk], vh[0], vh[1]);
        mma16816(o[2 * njp], pah[kk], vl[0], vl[1]);
        mma16816(o[2 * njp], pal[kk], vh[0], vh[1]);
        mma16816(o[2 * njp + 1], pah[kk], vh[2], vh[3]);
        mma16816(o[2 * njp + 1], pah[kk], vl[2], vl[3]);
        mma16816(o[2 * njp + 1], pal[kk], vh[2], vh[3]);
      }
    }
  }

  // ---- final row-sum reduction across the 4-lane groups ----
#pragma unroll
  for (int d = 1; d <= 2; d <<= 1) {
    lr0 += __shfl_xor_sync(0xffffffffu, lr0, d);
    lr1 += __shfl_xor_sync(0xffffffffu, lr1, d);
  }
  const float inv0 = 1.0f / lr0, inv1 = 1.0f / lr1;
  const int r0g = q0 + wid * 16 + gid;
#pragma unroll
  for (int nj = 0; nj < 8; nj++) {
    int col = h * DH + nj * 8 + 2 * tig;
    float2 v0 = make_float2(o[nj][0] * inv0, o[nj][1] * inv0);
    float2 v1 = make_float2(o[nj][2] * inv1, o[nj][3] * inv1);
    *(float2*)&out[((size_t)b * SS + r0g) * (NH * DH) + col] = v0;
    *(float2*)&out[((size_t)b * SS + r0g + 8) * (NH * DH) + col] = v1;
  }
}

extern "C" void kernel_launch(void* const* d_in, const int* in_sizes, int n_in,
                              void* d_out, int out_size) {
  const float* x = (const float*)d_in[0];
  const float* Wq = (const float*)d_in[1];
  const float* Wk = (const float*)d_in[2];
  const float* Wv = (const float*)d_in[3];
  float* out = (float*)d_out;

  const int n4 = BB * SS * DM / 4 + 3 * (WSZ / 4);
  split_kernel<<<(n4 + 255) / 256, 256>>>(x, Wq, Wk, Wv);
  proj_kernel<<<dim3(64, NH), 128>>>();
  attn_kernel<<<dim3(SS / 64, BB * NH), 128>>>(out);
}